// round 13
// baseline (speedup 1.0000x reference)
#include <cuda_runtime.h>
#include <cuda_bf16.h>
#include <cuda_fp16.h>
#include <cstdint>
#include <math.h>

#define BATCH 2
#define SEQ   2048
#define EMB   1024
#define HEADS 16
#define HDIM  64
#define TOK   (BATCH * SEQ)   // 4096

// ======================= PTX helpers (sm_80-era ISA only) =======================
__device__ __forceinline__ uint32_t smem_u32(const void* p) {
    uint32_t a;
    asm("{ .reg .u64 t; cvta.to.shared.u64 t, %1; cvt.u32.u64 %0, t; }"
        : "=r"(a) : "l"(p));
    return a;
}

#define LDSM_X4(r, a) \
    asm volatile("ldmatrix.sync.aligned.m8n8.x4.shared.b16 {%0,%1,%2,%3}, [%4];" \
                 : "=r"((r)[0]), "=r"((r)[1]), "=r"((r)[2]), "=r"((r)[3]) : "r"(a))

#define LDSM_X4T(r, a) \
    asm volatile("ldmatrix.sync.aligned.m8n8.x4.trans.shared.b16 {%0,%1,%2,%3}, [%4];" \
                 : "=r"((r)[0]), "=r"((r)[1]), "=r"((r)[2]), "=r"((r)[3]) : "r"(a))

#define MMA16816H(d, a, b) \
    asm volatile("mma.sync.aligned.m16n8k16.row.col.f32.f16.f16.f32 " \
                 "{%0,%1,%2,%3}, {%4,%5,%6,%7}, {%8,%9}, {%0,%1,%2,%3};" \
                 : "+f"((d)[0]), "+f"((d)[1]), "+f"((d)[2]), "+f"((d)[3]) \
                 : "r"((a)[0]), "r"((a)[1]), "r"((a)[2]), "r"((a)[3]), \
                   "r"((b)[0]), "r"((b)[1]))

#define CP_ASYNC16(saddr, gaddr) \
    asm volatile("cp.async.cg.shared.global [%0], [%1], 16;" :: "r"(saddr), "l"(gaddr))
#define CP_COMMIT() asm volatile("cp.async.commit_group;" ::: "memory")
#define CP_WAIT1() asm volatile("cp.async.wait_group 1;" ::: "memory")
#define CP_WAIT0() asm volatile("cp.async.wait_group 0;" ::: "memory")

__device__ __forceinline__ uint32_t packh2(float x, float y) {
    __half2 t = __floats2half2_rn(x, y);
    return *(uint32_t*)&t;
}

// ============ fused cvt: x + 4 weights -> single fp16 ============
__global__ void cvt_all_kernel(const float* __restrict__ x,
                               const float* __restrict__ w0, const float* __restrict__ w1,
                               const float* __restrict__ w2, const float* __restrict__ w3,
                               __half* __restrict__ xh,
                               __half* __restrict__ wq, __half* __restrict__ wk,
                               __half* __restrict__ wv, __half* __restrict__ wo) {
    const int z = blockIdx.y;
    int i = blockIdx.x * blockDim.x + threadIdx.x;
    const float* in;
    __half* o;
    int n4;
    if (z == 0)      { in = x;  o = xh; n4 = TOK * EMB / 4; }
    else if (z == 1) { in = w0; o = wq; n4 = EMB * EMB / 4; }
    else if (z == 2) { in = w1; o = wk; n4 = EMB * EMB / 4; }
    else if (z == 3) { in = w2; o = wv; n4 = EMB * EMB / 4; }
    else             { in = w3; o = wo; n4 = EMB * EMB / 4; }
    if (i >= n4) return;
    float4 v = *(const float4*)(in + i * 4);
    *(uint32_t*)(o + i * 4)     = packh2(v.x, v.y);
    *(uint32_t*)(o + i * 4 + 2) = packh2(v.z, v.w);
}

// ======== mma.sync fp16 GEMM: 3-stage ring, single sync/iter, 128x128 tile, 2 CTAs/SM ========
#define MT 128
#define NT 128
#define KT 64
#define NKTILE (EMB / KT)             // 16
#define TILE_H (128 * 128)            // 16KB (128 rows x 64 fp16)
#define GEMM_STAGE (2 * TILE_H)       // 32KB (A + B)
#define GEMM_SMEM (3 * GEMM_STAGE)    // 96KB -> 2 CTAs/SM

// Epilogue modes: 0 = fp32 C, 2 = fp16
__device__ __forceinline__ void gemm_core(
        const __half* __restrict__ A, const __half* __restrict__ B,
        float* __restrict__ C, __half* __restrict__ Ch,
        int mode, const uint32_t smb, int rowBase, int colBase) {
    const int tid = threadIdx.x;
    const int lane = tid & 31;
    const int wid = tid >> 5;
    const int wm = wid >> 2;          // 0..1 (64 rows each)
    const int wn = wid & 3;           // 0..3 (32 cols each)

    float acc[4][4][4];
#pragma unroll
    for (int mi = 0; mi < 4; mi++)
#pragma unroll
        for (int ni = 0; ni < 4; ni++)
#pragma unroll
            for (int j = 0; j < 4; j++) acc[mi][ni][j] = 0.f;

    auto load_stage = [&](int s, int kt) {
        const int k0 = kt * KT;
        uint32_t sb = smb + s * GEMM_STAGE;
#pragma unroll
        for (int it = 0; it < 8; it++) {
            int idx = tid + it * 256;      // 0..2047
            int arr = idx >> 10;           // 0: A, 1: B
            int rc  = idx & 1023;
            int row = rc >> 3;
            int ch  = rc & 7;
            uint32_t soff = sb + arr * TILE_H + row * 128 + ((ch ^ (row & 7)) * 16);
            const __half* src = arr ? B : A;
            int rb = arr ? colBase : rowBase;
            CP_ASYNC16(soff, src + (size_t)(rb + row) * EMB + k0 + ch * 8);
        }
        CP_COMMIT();
    };

    auto compute_stage = [&](int s) {
        const uint32_t sa = smb + s * GEMM_STAGE;
        const uint32_t sb2 = sa + TILE_H;
#pragma unroll
        for (int ks = 0; ks < 4; ks++) {
            uint32_t af[4][4];
#pragma unroll
            for (int mi = 0; mi < 4; mi++) {
                int row = wm * 64 + mi * 16 + (lane & 15);
                int ch = ks * 2 + (lane >> 4);
                uint32_t off = row * 128 + ((ch ^ (row & 7)) * 16);
                LDSM_X4(af[mi], sa + off);
            }
            uint32_t bf[4][2];
#pragma unroll
            for (int nip = 0; nip < 2; nip++) {
                int ni = nip * 2;
                int row = wn * 32 + (ni + (lane >> 4)) * 8 + (lane & 7);
                int ch = ks * 2 + ((lane >> 3) & 1);
                uint32_t off = row * 128 + ((ch ^ (row & 7)) * 16);
                uint32_t t4[4];
                LDSM_X4(t4, sb2 + off);
                bf[ni][0] = t4[0]; bf[ni][1] = t4[1];
                bf[ni + 1][0] = t4[2]; bf[ni + 1][1] = t4[3];
            }
#pragma unroll
            for (int mi = 0; mi < 4; mi++)
#pragma unroll
                for (int ni = 0; ni < 4; ni++)
                    MMA16816H(acc[mi][ni], af[mi], bf[ni]);
        }
    };

    // 3-stage ring, one barrier per iteration, loads issued before compute
    load_stage(0, 0);
    load_stage(1, 1);
    for (int t = 0; t < NKTILE; t++) {
        if (t < NKTILE - 1) CP_WAIT1(); else CP_WAIT0();
        __syncthreads();
        if (t + 2 < NKTILE) load_stage((t + 2) % 3, t + 2);
        compute_stage(t % 3);
    }

#pragma unroll
    for (int mi = 0; mi < 4; mi++) {
#pragma unroll
        for (int ni = 0; ni < 4; ni++) {
            int row = rowBase + wm * 64 + mi * 16 + (lane >> 2);
            int col = colBase + wn * 32 + ni * 8 + (lane & 3) * 2;
            size_t o0 = (size_t)row * EMB + col;
            size_t o1 = (size_t)(row + 8) * EMB + col;
            if (mode == 0) {
                *(float2*)&C[o0] = make_float2(acc[mi][ni][0], acc[mi][ni][1]);
                *(float2*)&C[o1] = make_float2(acc[mi][ni][2], acc[mi][ni][3]);
            } else {
                *(uint32_t*)&Ch[o0] = packh2(acc[mi][ni][0], acc[mi][ni][1]);
                *(uint32_t*)&Ch[o1] = packh2(acc[mi][ni][2], acc[mi][ni][3]);
            }
        }
    }
}

// Fused QKV (all single fp16 in and out)
__global__ void __launch_bounds__(256, 2)
gemm_qkv_kernel(const __half* __restrict__ xh,
                const __half* __restrict__ wq, const __half* __restrict__ wk,
                const __half* __restrict__ wv,
                __half* __restrict__ qh, __half* __restrict__ kh,
                __half* __restrict__ vh) {
    extern __shared__ char sm[];
    const int z = blockIdx.z;
    const __half* B = (z == 0) ? wq : (z == 1) ? wk : wv;
    __half* Ch = (z == 0) ? qh : (z == 1) ? kh : vh;
    gemm_core(xh, B, nullptr, Ch, 2, smem_u32(sm),
              blockIdx.y * MT, blockIdx.x * NT);
}

__global__ void __launch_bounds__(256, 2)
gemm_o_kernel(const __half* __restrict__ ah, const __half* __restrict__ wo,
              float* __restrict__ out) {
    extern __shared__ char sm[];
    gemm_core(ah, wo, out, nullptr, 0, smem_u32(sm),
              blockIdx.y * MT, blockIdx.x * NT);
}

// ============ Flash attention fp16, 3-stage KV ring, Q frags hoisted ============
#define ATILE (128 * 128)          // 16KB
#define KVTILE (64 * 128)          // 8KB
#define KVSTAGE (2 * KVTILE)       // 16KB: K, V
#define Q_OFF 0
#define KV_OFF ATILE               // 16KB
#define ATTN_SMEM (ATILE + 3 * KVSTAGE)  // 64KB -> 2 CTAs/SM

__global__ void __launch_bounds__(256, 2)
attn_mma_kernel(const __half* __restrict__ Qh, const __half* __restrict__ Kh,
                const __half* __restrict__ Vh, __half* __restrict__ Oh) {
    extern __shared__ char sm[];
    const uint32_t smb = smem_u32(sm);

    const int tid = threadIdx.x;
    const int lane = tid & 31;
    const int wid = tid >> 5;
    const int qt = gridDim.x - 1 - blockIdx.x;
    const int h  = blockIdx.y;
    const int b  = blockIdx.z;

    const size_t base = (size_t)b * SEQ * EMB + (size_t)h * HDIM;
    const __half* qp = Qh + base;
    const __half* kp = Kh + base;
    const __half* vp = Vh + base;

    auto load_kv = [&](int s, int kt) {
        const __half* bases[2] = {kp, vp};
#pragma unroll
        for (int it = 0; it < 4; it++) {
            int idx = tid + it * 256;      // 0..1023
            int arr = idx >> 9;            // 0: K, 1: V
            int rc  = idx & 511;
            int row = rc >> 3;
            int ch  = rc & 7;
            uint32_t soff = smb + KV_OFF + s * KVSTAGE + arr * KVTILE
                          + row * 128 + ((ch ^ (row & 7)) * 16);
            CP_ASYNC16(soff, bases[arr] + (size_t)(kt * 64 + row) * EMB + ch * 8);
        }
        CP_COMMIT();
    };

    // Q tile (own group, completes before kv0's wait passes)
#pragma unroll
    for (int it = 0; it < 4; it++) {
        int idx = tid + it * 256;      // 0..1023
        int row = idx >> 3;
        int ch  = idx & 7;
        uint32_t soff = smb + Q_OFF + row * 128 + ((ch ^ (row & 7)) * 16);
        CP_ASYNC16(soff, qp + (size_t)(qt * 128 + row) * EMB + ch * 8);
    }
    CP_COMMIT();

    const int ktmax = 2 * qt + 1;   // >= 1 always
    load_kv(0, 0);
    load_kv(1, 1);

    float o[8][4];
#pragma unroll
    for (int j = 0; j < 8; j++)
#pragma unroll
        for (int c = 0; c < 4; c++) o[j][c] = 0.f;
    float m0 = -1e30f, m1 = -1e30f, l0 = 0.f, l1 = 0.f;

    const float sscale = 0.125f;
    const int qrow0 = qt * 128 + wid * 16 + (lane >> 2);
    const uint32_t sq = smb + Q_OFF;

    uint32_t qf[4][4];   // Q fragments, loaded once at kt==0

    for (int kt = 0; kt <= ktmax; kt++) {
        if (kt < ktmax) CP_WAIT1(); else CP_WAIT0();
        __syncthreads();
        if (kt + 2 <= ktmax) load_kv((kt + 2) % 3, kt + 2);

        if (kt == 0) {
            // hoist Q frags into registers (Q smem never rewritten)
#pragma unroll
            for (int ks = 0; ks < 4; ks++) {
                int row = wid * 16 + (lane & 15);
                int ch = ks * 2 + (lane >> 4);
                uint32_t off = row * 128 + ((ch ^ (row & 7)) * 16);
                LDSM_X4(qf[ks], sq + off);
            }
        }

        bool active = (kt * 64 <= qt * 128 + wid * 16 + 15);
        if (active) {
            const int s = kt % 3;
            const uint32_t sk = smb + KV_OFF + s * KVSTAGE;
            const uint32_t sv = sk + KVTILE;

            // ---- S = Q K^T ----
            float sc[8][4];
#pragma unroll
            for (int j = 0; j < 8; j++)
#pragma unroll
                for (int c = 0; c < 4; c++) sc[j][c] = 0.f;

#pragma unroll
            for (int ks = 0; ks < 4; ks++) {
#pragma unroll
                for (int jp = 0; jp < 4; jp++) {
                    int j = jp * 2;
                    int row = (j + (lane >> 4)) * 8 + (lane & 7);
                    int ch = ks * 2 + ((lane >> 3) & 1);
                    uint32_t off = row * 128 + ((ch ^ (row & 7)) * 16);
                    uint32_t bf[4];
                    LDSM_X4(bf, sk + off);
                    MMA16816H(sc[j],     qf[ks], (&bf[0]));
                    MMA16816H(sc[j + 1], qf[ks], (&bf[2]));
                }
            }

            // ---- scale + causal mask ----
            bool diag = (kt * 64 + 63 > qt * 128 + wid * 16);
#pragma unroll
            for (int j = 0; j < 8; j++) {
                int col = kt * 64 + j * 8 + (lane & 3) * 2;
#pragma unroll
                for (int c = 0; c < 4; c++) {
                    float v = sc[j][c] * sscale;
                    if (diag) {
                        int cc = col + (c & 1);
                        int rr = qrow0 + ((c >= 2) ? 8 : 0);
                        if (cc > rr) v = -1e30f;
                    }
                    sc[j][c] = v;
                }
            }

            // ---- online softmax ----
            float mt0 = -1e30f, mt1 = -1e30f;
#pragma unroll
            for (int j = 0; j < 8; j++) {
                mt0 = fmaxf(mt0, fmaxf(sc[j][0], sc[j][1]));
                mt1 = fmaxf(mt1, fmaxf(sc[j][2], sc[j][3]));
            }
            mt0 = fmaxf(mt0, __shfl_xor_sync(0xffffffffu, mt0, 1));
            mt0 = fmaxf(mt0, __shfl_xor_sync(0xffffffffu, mt0, 2));
            mt1 = fmaxf(mt1, __shfl_xor_sync(0xffffffffu, mt1, 1));
            mt1 = fmaxf(mt1, __shfl_xor_sync(0xffffffffu, mt1, 2));

            float mn0 = fmaxf(m0, mt0), mn1 = fmaxf(m1, mt1);
            float corr0 = __expf(m0 - mn0), corr1 = __expf(m1 - mn1);

            float ps0 = 0.f, ps1 = 0.f;
#pragma unroll
            for (int j = 0; j < 8; j++) {
                float p0 = __expf(sc[j][0] - mn0);
                float p1 = __expf(sc[j][1] - mn0);
                float p2 = __expf(sc[j][2] - mn1);
                float p3 = __expf(sc[j][3] - mn1);
                sc[j][0] = p0; sc[j][1] = p1; sc[j][2] = p2; sc[j][3] = p3;
                ps0 += p0 + p1; ps1 += p2 + p3;
            }
            ps0 += __shfl_xor_sync(0xffffffffu, ps0, 1);
            ps0 += __shfl_xor_sync(0xffffffffu, ps0, 2);
            ps1 += __shfl_xor_sync(0xffffffffu, ps1, 1);
            ps1 += __shfl_xor_sync(0xffffffffu, ps1, 2);

            l0 = l0 * corr0 + ps0; m0 = mn0;
            l1 = l1 * corr1 + ps1; m1 = mn1;
#pragma unroll
            for (int j = 0; j < 8; j++) {
                o[j][0] *= corr0; o[j][1] *= corr0;
                o[j][2] *= corr1; o[j][3] *= corr1;
            }

            // ---- O += P V ----
#pragma unroll
            for (int ks = 0; ks < 4; ks++) {
                uint32_t ph[4];
                ph[0] = packh2(sc[2*ks][0],   sc[2*ks][1]);
                ph[1] = packh2(sc[2*ks][2],   sc[2*ks][3]);
                ph[2] = packh2(sc[2*ks+1][0], sc[2*ks+1][1]);
                ph[3] = packh2(sc[2*ks+1][2], sc[2*ks+1][3]);
#pragma unroll
                for (int j = 0; j < 4; j++) {
                    uint32_t bf[4];
                    int row = ks * 16 + (lane & 15);
                    int ch = j * 2 + (lane >> 4);
                    uint32_t off = row * 128 + ((ch ^ (row & 7)) * 16);
                    LDSM_X4T(bf, sv + off);
                    MMA16816H(o[2*j],     ph, (&bf[0]));
                    MMA16816H(o[2*j + 1], ph, (&bf[2]));
                }
            }
        }
    }

    // ---- normalize + single-fp16 store (for Wo GEMM) ----
    float inv0 = 1.f / l0, inv1 = 1.f / l1;
    const int row0 = b * SEQ + qt * 128 + wid * 16 + (lane >> 2);
#pragma unroll
    for (int j = 0; j < 8; j++) {
        float a0 = o[j][0] * inv0, a1 = o[j][1] * inv0;
        float a2 = o[j][2] * inv1, a3 = o[j][3] * inv1;
        size_t off0 = (size_t)row0 * EMB + h * HDIM + j * 8 + (lane & 3) * 2;
        size_t off1 = off0 + (size_t)8 * EMB;
        *(uint32_t*)&Oh[off0] = packh2(a0, a1);
        *(uint32_t*)&Oh[off1] = packh2(a2, a3);
    }
}

// ======================= Scratch =======================
__device__ __half g_xh[TOK * EMB];
__device__ __half g_qh[TOK * EMB], g_kh[TOK * EMB], g_vh[TOK * EMB];
__device__ __half g_ah[TOK * EMB];
__device__ __half g_wq[EMB * EMB], g_wk[EMB * EMB], g_wv[EMB * EMB], g_wo[EMB * EMB];

extern "C" void kernel_launch(void* const* d_in, const int* in_sizes, int n_in,
                              void* d_out, int out_size) {
    const float* x  = (const float*)d_in[0];
    const float* Wq = (const float*)d_in[2];
    const float* Wk = (const float*)d_in[3];
    const float* Wv = (const float*)d_in[4];
    const float* Wo = (const float*)d_in[5];
    float* out = (float*)d_out;

    __half *xh, *qh, *kh, *vh, *ah, *wq, *wk, *wv, *wo;
    cudaGetSymbolAddress((void**)&xh, g_xh);
    cudaGetSymbolAddress((void**)&qh, g_qh);
    cudaGetSymbolAddress((void**)&kh, g_kh);
    cudaGetSymbolAddress((void**)&vh, g_vh);
    cudaGetSymbolAddress((void**)&ah, g_ah);
    cudaGetSymbolAddress((void**)&wq, g_wq);
    cudaGetSymbolAddress((void**)&wk, g_wk);
    cudaGetSymbolAddress((void**)&wv, g_wv);
    cudaGetSymbolAddress((void**)&wo, g_wo);

    static bool attrs_set = false;
    if (!attrs_set) {
        cudaFuncSetAttribute(gemm_qkv_kernel,
                             cudaFuncAttributeMaxDynamicSharedMemorySize, GEMM_SMEM);
        cudaFuncSetAttribute(gemm_o_kernel,
                             cudaFuncAttributeMaxDynamicSharedMemorySize, GEMM_SMEM);
        cudaFuncSetAttribute(attn_mma_kernel,
                             cudaFuncAttributeMaxDynamicSharedMemorySize, ATTN_SMEM);
        attrs_set = true;
    }

    const int XB = (TOK * EMB / 4 + 255) / 256;
    dim3 cvtGrid(XB, 5);
    cvt_all_kernel<<<cvtGrid, 256>>>(x, Wq, Wk, Wv, Wo, xh, wq, wk, wv, wo);

    dim3 qkvGrid(EMB / NT, TOK / MT, 3);   // (8, 32, 3)
    gemm_qkv_kernel<<<qkvGrid, 256, GEMM_SMEM>>>(xh, wq, wk, wv, qh, kh, vh);

    dim3 attnGrid(SEQ / 128, HEADS, BATCH);   // (16, 16, 2)
    attn_mma_kernel<<<attnGrid, 256, ATTN_SMEM>>>(qh, kh, vh, ah);

    dim3 oGrid(EMB / NT, TOK / MT);   // (8, 32)
    gemm_o_kernel<<<oGrid, 256, GEMM_SMEM>>>(ah, wo, out);
}

// round 14
// speedup vs baseline: 1.0812x; 1.0812x over previous
#include <cuda_runtime.h>
#include <cuda_bf16.h>
#include <cuda_fp16.h>
#include <cstdint>
#include <math.h>

#define BATCH 2
#define SEQ   2048
#define EMB   1024
#define HEADS 16
#define HDIM  64
#define TOK   (BATCH * SEQ)   // 4096

// ======================= PTX helpers (sm_80-era ISA only) =======================
__device__ __forceinline__ uint32_t smem_u32(const void* p) {
    uint32_t a;
    asm("{ .reg .u64 t; cvta.to.shared.u64 t, %1; cvt.u32.u64 %0, t; }"
        : "=r"(a) : "l"(p));
    return a;
}

#define LDSM_X4(r, a) \
    asm volatile("ldmatrix.sync.aligned.m8n8.x4.shared.b16 {%0,%1,%2,%3}, [%4];" \
                 : "=r"((r)[0]), "=r"((r)[1]), "=r"((r)[2]), "=r"((r)[3]) : "r"(a))

#define LDSM_X4T(r, a) \
    asm volatile("ldmatrix.sync.aligned.m8n8.x4.trans.shared.b16 {%0,%1,%2,%3}, [%4];" \
                 : "=r"((r)[0]), "=r"((r)[1]), "=r"((r)[2]), "=r"((r)[3]) : "r"(a))

#define MMA16816H(d, a, b) \
    asm volatile("mma.sync.aligned.m16n8k16.row.col.f32.f16.f16.f32 " \
                 "{%0,%1,%2,%3}, {%4,%5,%6,%7}, {%8,%9}, {%0,%1,%2,%3};" \
                 : "+f"((d)[0]), "+f"((d)[1]), "+f"((d)[2]), "+f"((d)[3]) \
                 : "r"((a)[0]), "r"((a)[1]), "r"((a)[2]), "r"((a)[3]), \
                   "r"((b)[0]), "r"((b)[1]))

#define CP_ASYNC16(saddr, gaddr) \
    asm volatile("cp.async.cg.shared.global [%0], [%1], 16;" :: "r"(saddr), "l"(gaddr))
#define CP_COMMIT() asm volatile("cp.async.commit_group;" ::: "memory")
#define CP_WAIT1() asm volatile("cp.async.wait_group 1;" ::: "memory")
#define CP_WAIT0() asm volatile("cp.async.wait_group 0;" ::: "memory")

#define EX2_F16X2(out, in) \
    asm("ex2.approx.f16x2 %0, %1;" : "=r"(out) : "r"(in))

__device__ __forceinline__ uint32_t packh2(float x, float y) {
    __half2 t = __floats2half2_rn(x, y);
    return *(uint32_t*)&t;
}

// ============ fused cvt: x + 4 weights -> single fp16 ============
__global__ void cvt_all_kernel(const float* __restrict__ x,
                               const float* __restrict__ w0, const float* __restrict__ w1,
                               const float* __restrict__ w2, const float* __restrict__ w3,
                               __half* __restrict__ xh,
                               __half* __restrict__ wq, __half* __restrict__ wk,
                               __half* __restrict__ wv, __half* __restrict__ wo) {
    const int z = blockIdx.y;
    int i = blockIdx.x * blockDim.x + threadIdx.x;
    const float* in;
    __half* o;
    int n4;
    if (z == 0)      { in = x;  o = xh; n4 = TOK * EMB / 4; }
    else if (z == 1) { in = w0; o = wq; n4 = EMB * EMB / 4; }
    else if (z == 2) { in = w1; o = wk; n4 = EMB * EMB / 4; }
    else if (z == 3) { in = w2; o = wv; n4 = EMB * EMB / 4; }
    else             { in = w3; o = wo; n4 = EMB * EMB / 4; }
    if (i >= n4) return;
    float4 v = *(const float4*)(in + i * 4);
    *(uint32_t*)(o + i * 4)     = packh2(v.x, v.y);
    *(uint32_t*)(o + i * 4 + 2) = packh2(v.z, v.w);
}

// ======== mma.sync fp16 GEMM: single-term A and B. 128x128 tile, 2 CTAs/SM ========
#define MT 128
#define NT 128
#define KT 64
#define NKTILE (EMB / KT)             // 16
#define TILE_H (128 * 128)            // 16KB (128 rows x 64 fp16)
#define GEMM_STAGE (2 * TILE_H)       // 32KB (A + B)
#define GEMM_SMEM (2 * GEMM_STAGE)    // 64KB

// Epilogue modes: 0 = fp32 C, 2 = fp16
__device__ __forceinline__ void gemm_core(
        const __half* __restrict__ A, const __half* __restrict__ B,
        float* __restrict__ C, __half* __restrict__ Ch,
        int mode, const uint32_t smb, int rowBase, int colBase) {
    const int tid = threadIdx.x;
    const int lane = tid & 31;
    const int wid = tid >> 5;
    const int wm = wid >> 2;          // 0..1 (64 rows each)
    const int wn = wid & 3;           // 0..3 (32 cols each)

    float acc[4][4][4];
#pragma unroll
    for (int mi = 0; mi < 4; mi++)
#pragma unroll
        for (int ni = 0; ni < 4; ni++)
#pragma unroll
            for (int j = 0; j < 4; j++) acc[mi][ni][j] = 0.f;

    auto load_stage = [&](int s, int kt) {
        const int k0 = kt * KT;
        uint32_t sb = smb + s * GEMM_STAGE;
#pragma unroll
        for (int it = 0; it < 8; it++) {
            int idx = tid + it * 256;      // 0..2047
            int arr = idx >> 10;           // 0: A, 1: B
            int rc  = idx & 1023;
            int row = rc >> 3;
            int ch  = rc & 7;
            uint32_t soff = sb + arr * TILE_H + row * 128 + ((ch ^ (row & 7)) * 16);
            const __half* src = arr ? B : A;
            int rb = arr ? colBase : rowBase;
            CP_ASYNC16(soff, src + (size_t)(rb + row) * EMB + k0 + ch * 8);
        }
        CP_COMMIT();
    };

    auto compute_stage = [&](int s) {
        const uint32_t sa = smb + s * GEMM_STAGE;
        const uint32_t sb2 = sa + TILE_H;
#pragma unroll
        for (int ks = 0; ks < 4; ks++) {
            uint32_t af[4][4];
#pragma unroll
            for (int mi = 0; mi < 4; mi++) {
                int row = wm * 64 + mi * 16 + (lane & 15);
                int ch = ks * 2 + (lane >> 4);
                uint32_t off = row * 128 + ((ch ^ (row & 7)) * 16);
                LDSM_X4(af[mi], sa + off);
            }
            uint32_t bf[4][2];
#pragma unroll
            for (int nip = 0; nip < 2; nip++) {
                int ni = nip * 2;
                int row = wn * 32 + (ni + (lane >> 4)) * 8 + (lane & 7);
                int ch = ks * 2 + ((lane >> 3) & 1);
                uint32_t off = row * 128 + ((ch ^ (row & 7)) * 16);
                uint32_t t4[4];
                LDSM_X4(t4, sb2 + off);
                bf[ni][0] = t4[0]; bf[ni][1] = t4[1];
                bf[ni + 1][0] = t4[2]; bf[ni + 1][1] = t4[3];
            }
#pragma unroll
            for (int mi = 0; mi < 4; mi++)
#pragma unroll
                for (int ni = 0; ni < 4; ni++)
                    MMA16816H(acc[mi][ni], af[mi], bf[ni]);
        }
    };

    load_stage(0, 0);
    load_stage(1, 1);
    for (int t = 0; t < NKTILE; t++) {
        if (t < NKTILE - 2) CP_WAIT1(); else CP_WAIT0();
        __syncthreads();
        compute_stage(t & 1);
        __syncthreads();
        if (t + 2 < NKTILE) load_stage(t & 1, t + 2);
    }

#pragma unroll
    for (int mi = 0; mi < 4; mi++) {
#pragma unroll
        for (int ni = 0; ni < 4; ni++) {
            int row = rowBase + wm * 64 + mi * 16 + (lane >> 2);
            int col = colBase + wn * 32 + ni * 8 + (lane & 3) * 2;
            size_t o0 = (size_t)row * EMB + col;
            size_t o1 = (size_t)(row + 8) * EMB + col;
            if (mode == 0) {
                *(float2*)&C[o0] = make_float2(acc[mi][ni][0], acc[mi][ni][1]);
                *(float2*)&C[o1] = make_float2(acc[mi][ni][2], acc[mi][ni][3]);
            } else {
                *(uint32_t*)&Ch[o0] = packh2(acc[mi][ni][0], acc[mi][ni][1]);
                *(uint32_t*)&Ch[o1] = packh2(acc[mi][ni][2], acc[mi][ni][3]);
            }
        }
    }
}

// Fused QKV (all single fp16 in and out)
__global__ void __launch_bounds__(256, 2)
gemm_qkv_kernel(const __half* __restrict__ xh,
                const __half* __restrict__ wq, const __half* __restrict__ wk,
                const __half* __restrict__ wv,
                __half* __restrict__ qh, __half* __restrict__ kh,
                __half* __restrict__ vh) {
    extern __shared__ char sm[];
    const int z = blockIdx.z;
    const __half* B = (z == 0) ? wq : (z == 1) ? wk : wv;
    __half* Ch = (z == 0) ? qh : (z == 1) ? kh : vh;
    gemm_core(xh, B, nullptr, Ch, 2, smem_u32(sm),
              blockIdx.y * MT, blockIdx.x * NT);
}

__global__ void __launch_bounds__(256, 2)
gemm_o_kernel(const __half* __restrict__ ah, const __half* __restrict__ wo,
              float* __restrict__ out) {
    extern __shared__ char sm[];
    gemm_core(ah, wo, out, nullptr, 0, smem_u32(sm),
              blockIdx.y * MT, blockIdx.x * NT);
}

// ============ Flash attention fp16: base-2 softmax with ex2.approx.f16x2 ============
#define ATILE (128 * 128)          // 16KB
#define KVTILE (64 * 128)          // 8KB
#define KVSTAGE (2 * KVTILE)       // 16KB: K, V
#define Q_OFF 0
#define KV_OFF ATILE               // 16KB
#define ATTN_SMEM (ATILE + 2 * KVSTAGE)  // 48KB

__global__ void __launch_bounds__(256, 2)
attn_mma_kernel(const __half* __restrict__ Qh, const __half* __restrict__ Kh,
                const __half* __restrict__ Vh, __half* __restrict__ Oh) {
    extern __shared__ char sm[];
    const uint32_t smb = smem_u32(sm);

    const int tid = threadIdx.x;
    const int lane = tid & 31;
    const int wid = tid >> 5;
    const int qt = gridDim.x - 1 - blockIdx.x;
    const int h  = blockIdx.y;
    const int b  = blockIdx.z;

    const size_t base = (size_t)b * SEQ * EMB + (size_t)h * HDIM;
    const __half* qp = Qh + base;
    const __half* kp = Kh + base;
    const __half* vp = Vh + base;

    auto load_kv = [&](int s, int kt) {
        const __half* bases[2] = {kp, vp};
#pragma unroll
        for (int it = 0; it < 4; it++) {
            int idx = tid + it * 256;      // 0..1023
            int arr = idx >> 9;            // 0: K, 1: V
            int rc  = idx & 511;
            int row = rc >> 3;
            int ch  = rc & 7;
            uint32_t soff = smb + KV_OFF + s * KVSTAGE + arr * KVTILE
                          + row * 128 + ((ch ^ (row & 7)) * 16);
            CP_ASYNC16(soff, bases[arr] + (size_t)(kt * 64 + row) * EMB + ch * 8);
        }
        CP_COMMIT();
    };

    // group 0: Q tile (single)
#pragma unroll
    for (int it = 0; it < 4; it++) {
        int idx = tid + it * 256;      // 0..1023
        int row = idx >> 3;
        int ch  = idx & 7;
        uint32_t soff = smb + Q_OFF + row * 128 + ((ch ^ (row & 7)) * 16);
        CP_ASYNC16(soff, qp + (size_t)(qt * 128 + row) * EMB + ch * 8);
    }
    CP_COMMIT();

    const int ktmax = 2 * qt + 1;
    load_kv(0, 0);

    float o[8][4];
#pragma unroll
    for (int j = 0; j < 8; j++)
#pragma unroll
        for (int c = 0; c < 4; c++) o[j][c] = 0.f;
    float m0 = -1e30f, m1 = -1e30f, l0 = 0.f, l1 = 0.f;

    // base-2 domain: scores pre-multiplied by scale * log2(e)
    const float kscale = 0.125f * 1.44269504089f;
    const int qrow0 = qt * 128 + wid * 16 + (lane >> 2);
    const uint32_t sq = smb + Q_OFF;

    for (int kt = 0; kt <= ktmax; kt++) {
        if (kt < ktmax) { load_kv((kt + 1) & 1, kt + 1); CP_WAIT1(); }
        else           { CP_WAIT0(); }
        __syncthreads();

        bool active = (kt * 64 <= qt * 128 + wid * 16 + 15);
        if (active) {
            const int s = kt & 1;
            const uint32_t sk = smb + KV_OFF + s * KVSTAGE;
            const uint32_t sv = sk + KVTILE;

            // ---- S = Q K^T ----
            float sc[8][4];
#pragma unroll
            for (int j = 0; j < 8; j++)
#pragma unroll
                for (int c = 0; c < 4; c++) sc[j][c] = 0.f;

#pragma unroll
            for (int ks = 0; ks < 4; ks++) {
                uint32_t af[4];
                {
                    int row = wid * 16 + (lane & 15);
                    int ch = ks * 2 + (lane >> 4);
                    uint32_t off = row * 128 + ((ch ^ (row & 7)) * 16);
                    LDSM_X4(af, sq + off);
                }
#pragma unroll
                for (int jp = 0; jp < 4; jp++) {
                    int j = jp * 2;
                    int row = (j + (lane >> 4)) * 8 + (lane & 7);
                    int ch = ks * 2 + ((lane >> 3) & 1);
                    uint32_t off = row * 128 + ((ch ^ (row & 7)) * 16);
                    uint32_t bf[4];
                    LDSM_X4(bf, sk + off);
                    MMA16816H(sc[j],     af, (&bf[0]));
                    MMA16816H(sc[j + 1], af, (&bf[2]));
                }
            }

            // ---- scale (base-2) + causal mask ----
            bool diag = (kt * 64 + 63 > qt * 128 + wid * 16);
#pragma unroll
            for (int j = 0; j < 8; j++) {
                int col = kt * 64 + j * 8 + (lane & 3) * 2;
#pragma unroll
                for (int c = 0; c < 4; c++) {
                    float v = sc[j][c] * kscale;
                    if (diag) {
                        int cc = col + (c & 1);
                        int rr = qrow0 + ((c >= 2) ? 8 : 0);
                        if (cc > rr) v = -1e30f;
                    }
                    sc[j][c] = v;
                }
            }

            // ---- online softmax (base-2) ----
            float mt0 = -1e30f, mt1 = -1e30f;
#pragma unroll
            for (int j = 0; j < 8; j++) {
                mt0 = fmaxf(mt0, fmaxf(sc[j][0], sc[j][1]));
                mt1 = fmaxf(mt1, fmaxf(sc[j][2], sc[j][3]));
            }
            mt0 = fmaxf(mt0, __shfl_xor_sync(0xffffffffu, mt0, 1));
            mt0 = fmaxf(mt0, __shfl_xor_sync(0xffffffffu, mt0, 2));
            mt1 = fmaxf(mt1, __shfl_xor_sync(0xffffffffu, mt1, 1));
            mt1 = fmaxf(mt1, __shfl_xor_sync(0xffffffffu, mt1, 2));

            float mn0 = fmaxf(m0, mt0), mn1 = fmaxf(m1, mt1);
            float corr0 = exp2f(m0 - mn0), corr1 = exp2f(m1 - mn1);

            // P = exp2(s - m) computed in fp16x2; ph = ready-to-use A-fragments
            uint32_t ph[4][4];
            float ps0 = 0.f, ps1 = 0.f;
#pragma unroll
            for (int ks = 0; ks < 4; ks++) {
                uint32_t t0 = packh2(sc[2*ks][0]   - mn0, sc[2*ks][1]   - mn0);
                uint32_t t1 = packh2(sc[2*ks][2]   - mn1, sc[2*ks][3]   - mn1);
                uint32_t t2 = packh2(sc[2*ks+1][0] - mn0, sc[2*ks+1][1] - mn0);
                uint32_t t3 = packh2(sc[2*ks+1][2] - mn1, sc[2*ks+1][3] - mn1);
                EX2_F16X2(ph[ks][0], t0);
                EX2_F16X2(ph[ks][1], t1);
                EX2_F16X2(ph[ks][2], t2);
                EX2_F16X2(ph[ks][3], t3);
                float2 f0 = __half22float2(*(__half2*)&ph[ks][0]);
                float2 f1 = __half22float2(*(__half2*)&ph[ks][1]);
                float2 f2 = __half22float2(*(__half2*)&ph[ks][2]);
                float2 f3 = __half22float2(*(__half2*)&ph[ks][3]);
                ps0 += f0.x + f0.y + f2.x + f2.y;
                ps1 += f1.x + f1.y + f3.x + f3.y;
            }
            ps0 += __shfl_xor_sync(0xffffffffu, ps0, 1);
            ps0 += __shfl_xor_sync(0xffffffffu, ps0, 2);
            ps1 += __shfl_xor_sync(0xffffffffu, ps1, 1);
            ps1 += __shfl_xor_sync(0xffffffffu, ps1, 2);

            l0 = l0 * corr0 + ps0; m0 = mn0;
            l1 = l1 * corr1 + ps1; m1 = mn1;
#pragma unroll
            for (int j = 0; j < 8; j++) {
                o[j][0] *= corr0; o[j][1] *= corr0;
                o[j][2] *= corr1; o[j][3] *= corr1;
            }

            // ---- O += P V ----
#pragma unroll
            for (int ks = 0; ks < 4; ks++) {
#pragma unroll
                for (int j = 0; j < 4; j++) {
                    uint32_t bf[4];
                    int row = ks * 16 + (lane & 15);
                    int ch = j * 2 + (lane >> 4);
                    uint32_t off = row * 128 + ((ch ^ (row & 7)) * 16);
                    LDSM_X4T(bf, sv + off);
                    MMA16816H(o[2*j],     ph[ks], (&bf[0]));
                    MMA16816H(o[2*j + 1], ph[ks], (&bf[2]));
                }
            }
        }
        __syncthreads();
    }

    // ---- normalize + single-fp16 store (for Wo GEMM) ----
    float inv0 = 1.f / l0, inv1 = 1.f / l1;
    const int row0 = b * SEQ + qt * 128 + wid * 16 + (lane >> 2);
#pragma unroll
    for (int j = 0; j < 8; j++) {
        float a0 = o[j][0] * inv0, a1 = o[j][1] * inv0;
        float a2 = o[j][2] * inv1, a3 = o[j][3] * inv1;
        size_t off0 = (size_t)row0 * EMB + h * HDIM + j * 8 + (lane & 3) * 2;
        size_t off1 = off0 + (size_t)8 * EMB;
        *(uint32_t*)&Oh[off0] = packh2(a0, a1);
        *(uint32_t*)&Oh[off1] = packh2(a2, a3);
    }
}

// ======================= Scratch =======================
__device__ __half g_xh[TOK * EMB];
__device__ __half g_qh[TOK * EMB], g_kh[TOK * EMB], g_vh[TOK * EMB];
__device__ __half g_ah[TOK * EMB];
__device__ __half g_wq[EMB * EMB], g_wk[EMB * EMB], g_wv[EMB * EMB], g_wo[EMB * EMB];

extern "C" void kernel_launch(void* const* d_in, const int* in_sizes, int n_in,
                              void* d_out, int out_size) {
    const float* x  = (const float*)d_in[0];
    const float* Wq = (const float*)d_in[2];
    const float* Wk = (const float*)d_in[3];
    const float* Wv = (const float*)d_in[4];
    const float* Wo = (const float*)d_in[5];
    float* out = (float*)d_out;

    __half *xh, *qh, *kh, *vh, *ah, *wq, *wk, *wv, *wo;
    cudaGetSymbolAddress((void**)&xh, g_xh);
    cudaGetSymbolAddress((void**)&qh, g_qh);
    cudaGetSymbolAddress((void**)&kh, g_kh);
    cudaGetSymbolAddress((void**)&vh, g_vh);
    cudaGetSymbolAddress((void**)&ah, g_ah);
    cudaGetSymbolAddress((void**)&wq, g_wq);
    cudaGetSymbolAddress((void**)&wk, g_wk);
    cudaGetSymbolAddress((void**)&wv, g_wv);
    cudaGetSymbolAddress((void**)&wo, g_wo);

    static bool attrs_set = false;
    if (!attrs_set) {
        cudaFuncSetAttribute(gemm_qkv_kernel,
                             cudaFuncAttributeMaxDynamicSharedMemorySize, GEMM_SMEM);
        cudaFuncSetAttribute(gemm_o_kernel,
                             cudaFuncAttributeMaxDynamicSharedMemorySize, GEMM_SMEM);
        cudaFuncSetAttribute(attn_mma_kernel,
                             cudaFuncAttributeMaxDynamicSharedMemorySize, ATTN_SMEM);
        attrs_set = true;
    }

    const int XB = (TOK * EMB / 4 + 255) / 256;
    dim3 cvtGrid(XB, 5);
    cvt_all_kernel<<<cvtGrid, 256>>>(x, Wq, Wk, Wv, Wo, xh, wq, wk, wv, wo);

    dim3 qkvGrid(EMB / NT, TOK / MT, 3);   // (8, 32, 3)
    gemm_qkv_kernel<<<qkvGrid, 256, GEMM_SMEM>>>(xh, wq, wk, wv, qh, kh, vh);

    dim3 attnGrid(SEQ / 128, HEADS, BATCH);   // (16, 16, 2)
    attn_mma_kernel<<<attnGrid, 256, ATTN_SMEM>>>(qh, kh, vh, ah);

    dim3 oGrid(EMB / NT, TOK / MT);   // (8, 32)
    gemm_o_kernel<<<oGrid, 256, GEMM_SMEM>>>(ah, wo, out);
}

// round 15
// speedup vs baseline: 1.1165x; 1.0326x over previous
#include <cuda_runtime.h>
#include <cuda_bf16.h>
#include <cuda_fp16.h>
#include <cstdint>
#include <math.h>

#define BATCH 2
#define SEQ   2048
#define EMB   1024
#define HEADS 16
#define HDIM  64
#define TOK   (BATCH * SEQ)   // 4096

// ======================= PTX helpers (sm_80-era ISA only) =======================
__device__ __forceinline__ uint32_t smem_u32(const void* p) {
    uint32_t a;
    asm("{ .reg .u64 t; cvta.to.shared.u64 t, %1; cvt.u32.u64 %0, t; }"
        : "=r"(a) : "l"(p));
    return a;
}

#define LDSM_X4(r, a) \
    asm volatile("ldmatrix.sync.aligned.m8n8.x4.shared.b16 {%0,%1,%2,%3}, [%4];" \
                 : "=r"((r)[0]), "=r"((r)[1]), "=r"((r)[2]), "=r"((r)[3]) : "r"(a))

#define LDSM_X4T(r, a) \
    asm volatile("ldmatrix.sync.aligned.m8n8.x4.trans.shared.b16 {%0,%1,%2,%3}, [%4];" \
                 : "=r"((r)[0]), "=r"((r)[1]), "=r"((r)[2]), "=r"((r)[3]) : "r"(a))

#define MMA16816H(d, a, b) \
    asm volatile("mma.sync.aligned.m16n8k16.row.col.f32.f16.f16.f32 " \
                 "{%0,%1,%2,%3}, {%4,%5,%6,%7}, {%8,%9}, {%0,%1,%2,%3};" \
                 : "+f"((d)[0]), "+f"((d)[1]), "+f"((d)[2]), "+f"((d)[3]) \
                 : "r"((a)[0]), "r"((a)[1]), "r"((a)[2]), "r"((a)[3]), \
                   "r"((b)[0]), "r"((b)[1]))

#define CP_ASYNC16(saddr, gaddr) \
    asm volatile("cp.async.cg.shared.global [%0], [%1], 16;" :: "r"(saddr), "l"(gaddr))
#define CP_COMMIT() asm volatile("cp.async.commit_group;" ::: "memory")
#define CP_WAIT1() asm volatile("cp.async.wait_group 1;" ::: "memory")
#define CP_WAIT0() asm volatile("cp.async.wait_group 0;" ::: "memory")

#define EX2_F16X2(out, in) \
    asm("ex2.approx.f16x2 %0, %1;" : "=r"(out) : "r"(in))

__device__ __forceinline__ uint32_t packh2(float x, float y) {
    __half2 t = __floats2half2_rn(x, y);
    return *(uint32_t*)&t;
}

// ============ fused cvt: x + 4 weights -> single fp16 ============
__global__ void cvt_all_kernel(const float* __restrict__ x,
                               const float* __restrict__ w0, const float* __restrict__ w1,
                               const float* __restrict__ w2, const float* __restrict__ w3,
                               __half* __restrict__ xh,
                               __half* __restrict__ wq, __half* __restrict__ wk,
                               __half* __restrict__ wv, __half* __restrict__ wo) {
    const int z = blockIdx.y;
    int i = blockIdx.x * blockDim.x + threadIdx.x;
    const float* in;
    __half* o;
    int n4;
    if (z == 0)      { in = x;  o = xh; n4 = TOK * EMB / 4; }
    else if (z == 1) { in = w0; o = wq; n4 = EMB * EMB / 4; }
    else if (z == 2) { in = w1; o = wk; n4 = EMB * EMB / 4; }
    else if (z == 3) { in = w2; o = wv; n4 = EMB * EMB / 4; }
    else             { in = w3; o = wo; n4 = EMB * EMB / 4; }
    if (i >= n4) return;
    float4 v = *(const float4*)(in + i * 4);
    *(uint32_t*)(o + i * 4)     = packh2(v.x, v.y);
    *(uint32_t*)(o + i * 4 + 2) = packh2(v.z, v.w);
}

// ======== mma.sync fp16 GEMM: 128 threads, 4 warps of 64x64, 128x128 tile ========
#define MT 128
#define NT 128
#define KT 64
#define NKTILE (EMB / KT)             // 16
#define TILE_H (128 * 128)            // 16KB (128 rows x 64 fp16)
#define GEMM_STAGE (2 * TILE_H)       // 32KB (A + B)
#define GEMM_SMEM (2 * GEMM_STAGE)    // 64KB -> 2 CTAs/SM

// Epilogue modes: 0 = fp32 C, 2 = fp16
__device__ __forceinline__ void gemm_core(
        const __half* __restrict__ A, const __half* __restrict__ B,
        float* __restrict__ C, __half* __restrict__ Ch,
        int mode, const uint32_t smb, int rowBase, int colBase) {
    const int tid = threadIdx.x;
    const int lane = tid & 31;
    const int wid = tid >> 5;         // 0..3
    const int wm = wid >> 1;          // 0..1 (64 rows each)
    const int wn = wid & 1;           // 0..1 (64 cols each)

    float acc[4][8][4];
#pragma unroll
    for (int mi = 0; mi < 4; mi++)
#pragma unroll
        for (int ni = 0; ni < 8; ni++)
#pragma unroll
            for (int j = 0; j < 4; j++) acc[mi][ni][j] = 0.f;

    auto load_stage = [&](int s, int kt) {
        const int k0 = kt * KT;
        uint32_t sb = smb + s * GEMM_STAGE;
#pragma unroll
        for (int it = 0; it < 16; it++) {
            int idx = tid + it * 128;      // 0..2047
            int arr = idx >> 10;           // 0: A, 1: B
            int rc  = idx & 1023;
            int row = rc >> 3;
            int ch  = rc & 7;
            uint32_t soff = sb + arr * TILE_H + row * 128 + ((ch ^ (row & 7)) * 16);
            const __half* src = arr ? B : A;
            int rb = arr ? colBase : rowBase;
            CP_ASYNC16(soff, src + (size_t)(rb + row) * EMB + k0 + ch * 8);
        }
        CP_COMMIT();
    };

    auto compute_stage = [&](int s) {
        const uint32_t sa = smb + s * GEMM_STAGE;
        const uint32_t sb2 = sa + TILE_H;
#pragma unroll
        for (int ks = 0; ks < 4; ks++) {
            uint32_t af[4][4];
#pragma unroll
            for (int mi = 0; mi < 4; mi++) {
                int row = wm * 64 + mi * 16 + (lane & 15);
                int ch = ks * 2 + (lane >> 4);
                uint32_t off = row * 128 + ((ch ^ (row & 7)) * 16);
                LDSM_X4(af[mi], sa + off);
            }
            uint32_t bf[8][2];
#pragma unroll
            for (int nip = 0; nip < 4; nip++) {
                int ni = nip * 2;
                int row = wn * 64 + (ni + (lane >> 4)) * 8 + (lane & 7);
                int ch = ks * 2 + ((lane >> 3) & 1);
                uint32_t off = row * 128 + ((ch ^ (row & 7)) * 16);
                uint32_t t4[4];
                LDSM_X4(t4, sb2 + off);
                bf[ni][0] = t4[0]; bf[ni][1] = t4[1];
                bf[ni + 1][0] = t4[2]; bf[ni + 1][1] = t4[3];
            }
#pragma unroll
            for (int mi = 0; mi < 4; mi++)
#pragma unroll
                for (int ni = 0; ni < 8; ni++)
                    MMA16816H(acc[mi][ni], af[mi], bf[ni]);
        }
    };

    load_stage(0, 0);
    load_stage(1, 1);
    for (int t = 0; t < NKTILE; t++) {
        if (t < NKTILE - 2) CP_WAIT1(); else CP_WAIT0();
        __syncthreads();
        compute_stage(t & 1);
        __syncthreads();
        if (t + 2 < NKTILE) load_stage(t & 1, t + 2);
    }

#pragma unroll
    for (int mi = 0; mi < 4; mi++) {
#pragma unroll
        for (int ni = 0; ni < 8; ni++) {
            int row = rowBase + wm * 64 + mi * 16 + (lane >> 2);
            int col = colBase + wn * 64 + ni * 8 + (lane & 3) * 2;
            size_t o0 = (size_t)row * EMB + col;
            size_t o1 = (size_t)(row + 8) * EMB + col;
            if (mode == 0) {
                *(float2*)&C[o0] = make_float2(acc[mi][ni][0], acc[mi][ni][1]);
                *(float2*)&C[o1] = make_float2(acc[mi][ni][2], acc[mi][ni][3]);
            } else {
                *(uint32_t*)&Ch[o0] = packh2(acc[mi][ni][0], acc[mi][ni][1]);
                *(uint32_t*)&Ch[o1] = packh2(acc[mi][ni][2], acc[mi][ni][3]);
            }
        }
    }
}

// Fused QKV (all single fp16 in and out)
__global__ void __launch_bounds__(128, 2)
gemm_qkv_kernel(const __half* __restrict__ xh,
                const __half* __restrict__ wq, const __half* __restrict__ wk,
                const __half* __restrict__ wv,
                __half* __restrict__ qh, __half* __restrict__ kh,
                __half* __restrict__ vh) {
    extern __shared__ char sm[];
    const int z = blockIdx.z;
    const __half* B = (z == 0) ? wq : (z == 1) ? wk : wv;
    __half* Ch = (z == 0) ? qh : (z == 1) ? kh : vh;
    gemm_core(xh, B, nullptr, Ch, 2, smem_u32(sm),
              blockIdx.y * MT, blockIdx.x * NT);
}

__global__ void __launch_bounds__(128, 2)
gemm_o_kernel(const __half* __restrict__ ah, const __half* __restrict__ wo,
              float* __restrict__ out) {
    extern __shared__ char sm[];
    gemm_core(ah, wo, out, nullptr, 0, smem_u32(sm),
              blockIdx.y * MT, blockIdx.x * NT);
}

// ============ Flash attention fp16: base-2 softmax with ex2.approx.f16x2 ============
#define ATILE (128 * 128)          // 16KB
#define KVTILE (64 * 128)          // 8KB
#define KVSTAGE (2 * KVTILE)       // 16KB: K, V
#define Q_OFF 0
#define KV_OFF ATILE               // 16KB
#define ATTN_SMEM (ATILE + 2 * KVSTAGE)  // 48KB

__global__ void __launch_bounds__(256, 2)
attn_mma_kernel(const __half* __restrict__ Qh, const __half* __restrict__ Kh,
                const __half* __restrict__ Vh, __half* __restrict__ Oh) {
    extern __shared__ char sm[];
    const uint32_t smb = smem_u32(sm);

    const int tid = threadIdx.x;
    const int lane = tid & 31;
    const int wid = tid >> 5;
    const int qt = gridDim.x - 1 - blockIdx.x;
    const int h  = blockIdx.y;
    const int b  = blockIdx.z;

    const size_t base = (size_t)b * SEQ * EMB + (size_t)h * HDIM;
    const __half* qp = Qh + base;
    const __half* kp = Kh + base;
    const __half* vp = Vh + base;

    auto load_kv = [&](int s, int kt) {
        const __half* bases[2] = {kp, vp};
#pragma unroll
        for (int it = 0; it < 4; it++) {
            int idx = tid + it * 256;      // 0..1023
            int arr = idx >> 9;            // 0: K, 1: V
            int rc  = idx & 511;
            int row = rc >> 3;
            int ch  = rc & 7;
            uint32_t soff = smb + KV_OFF + s * KVSTAGE + arr * KVTILE
                          + row * 128 + ((ch ^ (row & 7)) * 16);
            CP_ASYNC16(soff, bases[arr] + (size_t)(kt * 64 + row) * EMB + ch * 8);
        }
        CP_COMMIT();
    };

    // group 0: Q tile (single)
#pragma unroll
    for (int it = 0; it < 4; it++) {
        int idx = tid + it * 256;      // 0..1023
        int row = idx >> 3;
        int ch  = idx & 7;
        uint32_t soff = smb + Q_OFF + row * 128 + ((ch ^ (row & 7)) * 16);
        CP_ASYNC16(soff, qp + (size_t)(qt * 128 + row) * EMB + ch * 8);
    }
    CP_COMMIT();

    const int ktmax = 2 * qt + 1;
    load_kv(0, 0);

    float o[8][4];
#pragma unroll
    for (int j = 0; j < 8; j++)
#pragma unroll
        for (int c = 0; c < 4; c++) o[j][c] = 0.f;
    float m0 = -1e30f, m1 = -1e30f, l0 = 0.f, l1 = 0.f;

    // base-2 domain: scores pre-multiplied by scale * log2(e)
    const float kscale = 0.125f * 1.44269504089f;
    const int qrow0 = qt * 128 + wid * 16 + (lane >> 2);
    const uint32_t sq = smb + Q_OFF;

    for (int kt = 0; kt <= ktmax; kt++) {
        if (kt < ktmax) { load_kv((kt + 1) & 1, kt + 1); CP_WAIT1(); }
        else           { CP_WAIT0(); }
        __syncthreads();

        bool active = (kt * 64 <= qt * 128 + wid * 16 + 15);
        if (active) {
            const int s = kt & 1;
            const uint32_t sk = smb + KV_OFF + s * KVSTAGE;
            const uint32_t sv = sk + KVTILE;

            // ---- S = Q K^T ----
            float sc[8][4];
#pragma unroll
            for (int j = 0; j < 8; j++)
#pragma unroll
                for (int c = 0; c < 4; c++) sc[j][c] = 0.f;

#pragma unroll
            for (int ks = 0; ks < 4; ks++) {
                uint32_t af[4];
                {
                    int row = wid * 16 + (lane & 15);
                    int ch = ks * 2 + (lane >> 4);
                    uint32_t off = row * 128 + ((ch ^ (row & 7)) * 16);
                    LDSM_X4(af, sq + off);
                }
#pragma unroll
                for (int jp = 0; jp < 4; jp++) {
                    int j = jp * 2;
                    int row = (j + (lane >> 4)) * 8 + (lane & 7);
                    int ch = ks * 2 + ((lane >> 3) & 1);
                    uint32_t off = row * 128 + ((ch ^ (row & 7)) * 16);
                    uint32_t bf[4];
                    LDSM_X4(bf, sk + off);
                    MMA16816H(sc[j],     af, (&bf[0]));
                    MMA16816H(sc[j + 1], af, (&bf[2]));
                }
            }

            // ---- scale (base-2) + causal mask ----
            bool diag = (kt * 64 + 63 > qt * 128 + wid * 16);
#pragma unroll
            for (int j = 0; j < 8; j++) {
                int col = kt * 64 + j * 8 + (lane & 3) * 2;
#pragma unroll
                for (int c = 0; c < 4; c++) {
                    float v = sc[j][c] * kscale;
                    if (diag) {
                        int cc = col + (c & 1);
                        int rr = qrow0 + ((c >= 2) ? 8 : 0);
                        if (cc > rr) v = -1e30f;
                    }
                    sc[j][c] = v;
                }
            }

            // ---- online softmax (base-2) ----
            float mt0 = -1e30f, mt1 = -1e30f;
#pragma unroll
            for (int j = 0; j < 8; j++) {
                mt0 = fmaxf(mt0, fmaxf(sc[j][0], sc[j][1]));
                mt1 = fmaxf(mt1, fmaxf(sc[j][2], sc[j][3]));
            }
            mt0 = fmaxf(mt0, __shfl_xor_sync(0xffffffffu, mt0, 1));
            mt0 = fmaxf(mt0, __shfl_xor_sync(0xffffffffu, mt0, 2));
            mt1 = fmaxf(mt1, __shfl_xor_sync(0xffffffffu, mt1, 1));
            mt1 = fmaxf(mt1, __shfl_xor_sync(0xffffffffu, mt1, 2));

            float mn0 = fmaxf(m0, mt0), mn1 = fmaxf(m1, mt1);
            float corr0 = exp2f(m0 - mn0), corr1 = exp2f(m1 - mn1);

            // P = exp2(s - m) in fp16x2; ph = ready-to-use A-fragments
            uint32_t ph[4][4];
            float ps0 = 0.f, ps1 = 0.f;
#pragma unroll
            for (int ks = 0; ks < 4; ks++) {
                uint32_t t0 = packh2(sc[2*ks][0]   - mn0, sc[2*ks][1]   - mn0);
                uint32_t t1 = packh2(sc[2*ks][2]   - mn1, sc[2*ks][3]   - mn1);
                uint32_t t2 = packh2(sc[2*ks+1][0] - mn0, sc[2*ks+1][1] - mn0);
                uint32_t t3 = packh2(sc[2*ks+1][2] - mn1, sc[2*ks+1][3] - mn1);
                EX2_F16X2(ph[ks][0], t0);
                EX2_F16X2(ph[ks][1], t1);
                EX2_F16X2(ph[ks][2], t2);
                EX2_F16X2(ph[ks][3], t3);
                float2 f0 = __half22float2(*(__half2*)&ph[ks][0]);
                float2 f1 = __half22float2(*(__half2*)&ph[ks][1]);
                float2 f2 = __half22float2(*(__half2*)&ph[ks][2]);
                float2 f3 = __half22float2(*(__half2*)&ph[ks][3]);
                ps0 += f0.x + f0.y + f2.x + f2.y;
                ps1 += f1.x + f1.y + f3.x + f3.y;
            }
            ps0 += __shfl_xor_sync(0xffffffffu, ps0, 1);
            ps0 += __shfl_xor_sync(0xffffffffu, ps0, 2);
            ps1 += __shfl_xor_sync(0xffffffffu, ps1, 1);
            ps1 += __shfl_xor_sync(0xffffffffu, ps1, 2);

            l0 = l0 * corr0 + ps0; m0 = mn0;
            l1 = l1 * corr1 + ps1; m1 = mn1;
#pragma unroll
            for (int j = 0; j < 8; j++) {
                o[j][0] *= corr0; o[j][1] *= corr0;
                o[j][2] *= corr1; o[j][3] *= corr1;
            }

            // ---- O += P V ----
#pragma unroll
            for (int ks = 0; ks < 4; ks++) {
#pragma unroll
                for (int j = 0; j < 4; j++) {
                    uint32_t bf[4];
                    int row = ks * 16 + (lane & 15);
                    int ch = j * 2 + (lane >> 4);
                    uint32_t off = row * 128 + ((ch ^ (row & 7)) * 16);
                    LDSM_X4T(bf, sv + off);
                    MMA16816H(o[2*j],     ph[ks], (&bf[0]));
                    MMA16816H(o[2*j + 1], ph[ks], (&bf[2]));
                }
            }
        }
        __syncthreads();
    }

    // ---- normalize + single-fp16 store (for Wo GEMM) ----
    float inv0 = 1.f / l0, inv1 = 1.f / l1;
    const int row0 = b * SEQ + qt * 128 + wid * 16 + (lane >> 2);
#pragma unroll
    for (int j = 0; j < 8; j++) {
        float a0 = o[j][0] * inv0, a1 = o[j][1] * inv0;
        float a2 = o[j][2] * inv1, a3 = o[j][3] * inv1;
        size_t off0 = (size_t)row0 * EMB + h * HDIM + j * 8 + (lane & 3) * 2;
        size_t off1 = off0 + (size_t)8 * EMB;
        *(uint32_t*)&Oh[off0] = packh2(a0, a1);
        *(uint32_t*)&Oh[off1] = packh2(a2, a3);
    }
}

// ======================= Scratch =======================
__device__ __half g_xh[TOK * EMB];
__device__ __half g_qh[TOK * EMB], g_kh[TOK * EMB], g_vh[TOK * EMB];
__device__ __half g_ah[TOK * EMB];
__device__ __half g_wq[EMB * EMB], g_wk[EMB * EMB], g_wv[EMB * EMB], g_wo[EMB * EMB];

extern "C" void kernel_launch(void* const* d_in, const int* in_sizes, int n_in,
                              void* d_out, int out_size) {
    const float* x  = (const float*)d_in[0];
    const float* Wq = (const float*)d_in[2];
    const float* Wk = (const float*)d_in[3];
    const float* Wv = (const float*)d_in[4];
    const float* Wo = (const float*)d_in[5];
    float* out = (float*)d_out;

    __half *xh, *qh, *kh, *vh, *ah, *wq, *wk, *wv, *wo;
    cudaGetSymbolAddress((void**)&xh, g_xh);
    cudaGetSymbolAddress((void**)&qh, g_qh);
    cudaGetSymbolAddress((void**)&kh, g_kh);
    cudaGetSymbolAddress((void**)&vh, g_vh);
    cudaGetSymbolAddress((void**)&ah, g_ah);
    cudaGetSymbolAddress((void**)&wq, g_wq);
    cudaGetSymbolAddress((void**)&wk, g_wk);
    cudaGetSymbolAddress((void**)&wv, g_wv);
    cudaGetSymbolAddress((void**)&wo, g_wo);

    static bool attrs_set = false;
    if (!attrs_set) {
        cudaFuncSetAttribute(gemm_qkv_kernel,
                             cudaFuncAttributeMaxDynamicSharedMemorySize, GEMM_SMEM);
        cudaFuncSetAttribute(gemm_o_kernel,
                             cudaFuncAttributeMaxDynamicSharedMemorySize, GEMM_SMEM);
        cudaFuncSetAttribute(attn_mma_kernel,
                             cudaFuncAttributeMaxDynamicSharedMemorySize, ATTN_SMEM);
        attrs_set = true;
    }

    const int XB = (TOK * EMB / 4 + 255) / 256;
    dim3 cvtGrid(XB, 5);
    cvt_all_kernel<<<cvtGrid, 256>>>(x, Wq, Wk, Wv, Wo, xh, wq, wk, wv, wo);

    dim3 qkvGrid(EMB / NT, TOK / MT, 3);   // (8, 32, 3)
    gemm_qkv_kernel<<<qkvGrid, 128, GEMM_SMEM>>>(xh, wq, wk, wv, qh, kh, vh);

    dim3 attnGrid(SEQ / 128, HEADS, BATCH);   // (16, 16, 2)
    attn_mma_kernel<<<attnGrid, 256, ATTN_SMEM>>>(qh, kh, vh, ah);

    dim3 oGrid(EMB / NT, TOK / MT);   // (8, 32)
    gemm_o_kernel<<<oGrid, 128, GEMM_SMEM>>>(ah, wo, out);
}

// round 16
// speedup vs baseline: 1.1360x; 1.0175x over previous
#include <cuda_runtime.h>
#include <cuda_bf16.h>
#include <cuda_fp16.h>
#include <cstdint>
#include <math.h>

#define BATCH 2
#define SEQ   2048
#define EMB   1024
#define HEADS 16
#define HDIM  64
#define TOK   (BATCH * SEQ)   // 4096

// ======================= PTX helpers (sm_80-era ISA only) =======================
__device__ __forceinline__ uint32_t smem_u32(const void* p) {
    uint32_t a;
    asm("{ .reg .u64 t; cvta.to.shared.u64 t, %1; cvt.u32.u64 %0, t; }"
        : "=r"(a) : "l"(p));
    return a;
}

#define LDSM_X4(r, a) \
    asm volatile("ldmatrix.sync.aligned.m8n8.x4.shared.b16 {%0,%1,%2,%3}, [%4];" \
                 : "=r"((r)[0]), "=r"((r)[1]), "=r"((r)[2]), "=r"((r)[3]) : "r"(a))

#define LDSM_X4T(r, a) \
    asm volatile("ldmatrix.sync.aligned.m8n8.x4.trans.shared.b16 {%0,%1,%2,%3}, [%4];" \
                 : "=r"((r)[0]), "=r"((r)[1]), "=r"((r)[2]), "=r"((r)[3]) : "r"(a))

#define MMA16816H(d, a, b) \
    asm volatile("mma.sync.aligned.m16n8k16.row.col.f32.f16.f16.f32 " \
                 "{%0,%1,%2,%3}, {%4,%5,%6,%7}, {%8,%9}, {%0,%1,%2,%3};" \
                 : "+f"((d)[0]), "+f"((d)[1]), "+f"((d)[2]), "+f"((d)[3]) \
                 : "r"((a)[0]), "r"((a)[1]), "r"((a)[2]), "r"((a)[3]), \
                   "r"((b)[0]), "r"((b)[1]))

#define CP_ASYNC16(saddr, gaddr) \
    asm volatile("cp.async.cg.shared.global [%0], [%1], 16;" :: "r"(saddr), "l"(gaddr))
#define CP_COMMIT() asm volatile("cp.async.commit_group;" ::: "memory")
#define CP_WAIT1() asm volatile("cp.async.wait_group 1;" ::: "memory")
#define CP_WAIT0() asm volatile("cp.async.wait_group 0;" ::: "memory")

#define EX2_F16X2(out, in) \
    asm("ex2.approx.f16x2 %0, %1;" : "=r"(out) : "r"(in))

__device__ __forceinline__ uint32_t packh2(float x, float y) {
    __half2 t = __floats2half2_rn(x, y);
    return *(uint32_t*)&t;
}

// ============ fused cvt: x + 4 weights -> single fp16 ============
__global__ void cvt_all_kernel(const float* __restrict__ x,
                               const float* __restrict__ w0, const float* __restrict__ w1,
                               const float* __restrict__ w2, const float* __restrict__ w3,
                               __half* __restrict__ xh,
                               __half* __restrict__ wq, __half* __restrict__ wk,
                               __half* __restrict__ wv, __half* __restrict__ wo) {
    const int z = blockIdx.y;
    int i = blockIdx.x * blockDim.x + threadIdx.x;
    const float* in;
    __half* o;
    int n4;
    if (z == 0)      { in = x;  o = xh; n4 = TOK * EMB / 4; }
    else if (z == 1) { in = w0; o = wq; n4 = EMB * EMB / 4; }
    else if (z == 2) { in = w1; o = wk; n4 = EMB * EMB / 4; }
    else if (z == 3) { in = w2; o = wv; n4 = EMB * EMB / 4; }
    else             { in = w3; o = wo; n4 = EMB * EMB / 4; }
    if (i >= n4) return;
    float4 v = *(const float4*)(in + i * 4);
    *(uint32_t*)(o + i * 4)     = packh2(v.x, v.y);
    *(uint32_t*)(o + i * 4 + 2) = packh2(v.z, v.w);
}

// ======== mma.sync fp16 GEMM: 128 threads, 4 warps of 64x64, 128x128 tile ========
#define MT 128
#define NT 128
#define KT 64
#define NKTILE (EMB / KT)             // 16
#define TILE_H (128 * 128)            // 16KB (128 rows x 64 fp16)
#define GEMM_STAGE (2 * TILE_H)       // 32KB (A + B)
#define GEMM_SMEM (2 * GEMM_STAGE)    // 64KB -> 2 CTAs/SM

// Epilogue modes: 0 = fp32 C, 2 = fp16
__device__ __forceinline__ void gemm_core(
        const __half* __restrict__ A, const __half* __restrict__ B,
        float* __restrict__ C, __half* __restrict__ Ch,
        int mode, const uint32_t smb, int rowBase, int colBase) {
    const int tid = threadIdx.x;
    const int lane = tid & 31;
    const int wid = tid >> 5;         // 0..3
    const int wm = wid >> 1;          // 0..1 (64 rows each)
    const int wn = wid & 1;           // 0..1 (64 cols each)

    float acc[4][8][4];
#pragma unroll
    for (int mi = 0; mi < 4; mi++)
#pragma unroll
        for (int ni = 0; ni < 8; ni++)
#pragma unroll
            for (int j = 0; j < 4; j++) acc[mi][ni][j] = 0.f;

    auto load_stage = [&](int s, int kt) {
        const int k0 = kt * KT;
        uint32_t sb = smb + s * GEMM_STAGE;
#pragma unroll
        for (int it = 0; it < 16; it++) {
            int idx = tid + it * 128;      // 0..2047
            int arr = idx >> 10;           // 0: A, 1: B
            int rc  = idx & 1023;
            int row = rc >> 3;
            int ch  = rc & 7;
            uint32_t soff = sb + arr * TILE_H + row * 128 + ((ch ^ (row & 7)) * 16);
            const __half* src = arr ? B : A;
            int rb = arr ? colBase : rowBase;
            CP_ASYNC16(soff, src + (size_t)(rb + row) * EMB + k0 + ch * 8);
        }
        CP_COMMIT();
    };

    auto compute_stage = [&](int s) {
        const uint32_t sa = smb + s * GEMM_STAGE;
        const uint32_t sb2 = sa + TILE_H;
#pragma unroll
        for (int ks = 0; ks < 4; ks++) {
            uint32_t af[4][4];
#pragma unroll
            for (int mi = 0; mi < 4; mi++) {
                int row = wm * 64 + mi * 16 + (lane & 15);
                int ch = ks * 2 + (lane >> 4);
                uint32_t off = row * 128 + ((ch ^ (row & 7)) * 16);
                LDSM_X4(af[mi], sa + off);
            }
            uint32_t bf[8][2];
#pragma unroll
            for (int nip = 0; nip < 4; nip++) {
                int ni = nip * 2;
                int row = wn * 64 + (ni + (lane >> 4)) * 8 + (lane & 7);
                int ch = ks * 2 + ((lane >> 3) & 1);
                uint32_t off = row * 128 + ((ch ^ (row & 7)) * 16);
                uint32_t t4[4];
                LDSM_X4(t4, sb2 + off);
                bf[ni][0] = t4[0]; bf[ni][1] = t4[1];
                bf[ni + 1][0] = t4[2]; bf[ni + 1][1] = t4[3];
            }
#pragma unroll
            for (int mi = 0; mi < 4; mi++)
#pragma unroll
                for (int ni = 0; ni < 8; ni++)
                    MMA16816H(acc[mi][ni], af[mi], bf[ni]);
        }
    };

    load_stage(0, 0);
    load_stage(1, 1);
    for (int t = 0; t < NKTILE; t++) {
        if (t < NKTILE - 2) CP_WAIT1(); else CP_WAIT0();
        __syncthreads();
        compute_stage(t & 1);
        __syncthreads();
        if (t + 2 < NKTILE) load_stage(t & 1, t + 2);
    }

#pragma unroll
    for (int mi = 0; mi < 4; mi++) {
#pragma unroll
        for (int ni = 0; ni < 8; ni++) {
            int row = rowBase + wm * 64 + mi * 16 + (lane >> 2);
            int col = colBase + wn * 64 + ni * 8 + (lane & 3) * 2;
            size_t o0 = (size_t)row * EMB + col;
            size_t o1 = (size_t)(row + 8) * EMB + col;
            if (mode == 0) {
                *(float2*)&C[o0] = make_float2(acc[mi][ni][0], acc[mi][ni][1]);
                *(float2*)&C[o1] = make_float2(acc[mi][ni][2], acc[mi][ni][3]);
            } else {
                *(uint32_t*)&Ch[o0] = packh2(acc[mi][ni][0], acc[mi][ni][1]);
                *(uint32_t*)&Ch[o1] = packh2(acc[mi][ni][2], acc[mi][ni][3]);
            }
        }
    }
}

// Fused QKV (all single fp16 in and out)
__global__ void __launch_bounds__(128, 2)
gemm_qkv_kernel(const __half* __restrict__ xh,
                const __half* __restrict__ wq, const __half* __restrict__ wk,
                const __half* __restrict__ wv,
                __half* __restrict__ qh, __half* __restrict__ kh,
                __half* __restrict__ vh) {
    extern __shared__ char sm[];
    const int z = blockIdx.z;
    const __half* B = (z == 0) ? wq : (z == 1) ? wk : wv;
    __half* Ch = (z == 0) ? qh : (z == 1) ? kh : vh;
    gemm_core(xh, B, nullptr, Ch, 2, smem_u32(sm),
              blockIdx.y * MT, blockIdx.x * NT);
}

__global__ void __launch_bounds__(128, 2)
gemm_o_kernel(const __half* __restrict__ ah, const __half* __restrict__ wo,
              float* __restrict__ out) {
    extern __shared__ char sm[];
    gemm_core(ah, wo, out, nullptr, 0, smem_u32(sm),
              blockIdx.y * MT, blockIdx.x * NT);
}

// ==== Flash attention fp16: 128 threads, 4 warps x 32 q-rows, ex2 softmax ====
#define ATILE (128 * 128)          // 16KB
#define KVTILE (64 * 128)          // 8KB
#define KVSTAGE (2 * KVTILE)       // 16KB: K, V
#define Q_OFF 0
#define KV_OFF ATILE               // 16KB
#define ATTN_SMEM (ATILE + 2 * KVSTAGE)  // 48KB

__global__ void __launch_bounds__(128, 2)
attn_mma_kernel(const __half* __restrict__ Qh, const __half* __restrict__ Kh,
                const __half* __restrict__ Vh, __half* __restrict__ Oh) {
    extern __shared__ char sm[];
    const uint32_t smb = smem_u32(sm);

    const int tid = threadIdx.x;
    const int lane = tid & 31;
    const int wid = tid >> 5;          // 0..3, warp owns q-rows [wid*32, wid*32+32)
    const int qt = gridDim.x - 1 - blockIdx.x;
    const int h  = blockIdx.y;
    const int b  = blockIdx.z;

    const size_t base = (size_t)b * SEQ * EMB + (size_t)h * HDIM;
    const __half* qp = Qh + base;
    const __half* kp = Kh + base;
    const __half* vp = Vh + base;

    auto load_kv = [&](int s, int kt) {
        const __half* bases[2] = {kp, vp};
#pragma unroll
        for (int it = 0; it < 8; it++) {
            int idx = tid + it * 128;      // 0..1023
            int arr = idx >> 9;            // 0: K, 1: V
            int rc  = idx & 511;
            int row = rc >> 3;
            int ch  = rc & 7;
            uint32_t soff = smb + KV_OFF + s * KVSTAGE + arr * KVTILE
                          + row * 128 + ((ch ^ (row & 7)) * 16);
            CP_ASYNC16(soff, bases[arr] + (size_t)(kt * 64 + row) * EMB + ch * 8);
        }
        CP_COMMIT();
    };

    // group 0: Q tile
#pragma unroll
    for (int it = 0; it < 8; it++) {
        int idx = tid + it * 128;      // 0..1023
        int row = idx >> 3;
        int ch  = idx & 7;
        uint32_t soff = smb + Q_OFF + row * 128 + ((ch ^ (row & 7)) * 16);
        CP_ASYNC16(soff, qp + (size_t)(qt * 128 + row) * EMB + ch * 8);
    }
    CP_COMMIT();

    const int ktmax = 2 * qt + 1;
    load_kv(0, 0);

    // o[mi][hd-frag][4], softmax state per mi per half-row
    float o[2][8][4];
#pragma unroll
    for (int mi = 0; mi < 2; mi++)
#pragma unroll
        for (int j = 0; j < 8; j++)
#pragma unroll
            for (int c = 0; c < 4; c++) o[mi][j][c] = 0.f;
    float m[2][2] = {{-1e30f, -1e30f}, {-1e30f, -1e30f}};
    float l[2][2] = {{0.f, 0.f}, {0.f, 0.f}};

    const float kscale = 0.125f * 1.44269504089f;   // scale * log2(e)
    const uint32_t sq = smb + Q_OFF;
    const int wrow = qt * 128 + wid * 32;           // warp's first q-row

    for (int kt = 0; kt <= ktmax; kt++) {
        if (kt < ktmax) { load_kv((kt + 1) & 1, kt + 1); CP_WAIT1(); }
        else           { CP_WAIT0(); }
        __syncthreads();

        bool active = (kt * 64 <= wrow + 31);
        if (active) {
            const int s = kt & 1;
            const uint32_t sk = smb + KV_OFF + s * KVSTAGE;
            const uint32_t sv = sk + KVTILE;

            // ---- S = Q K^T : sc[mi][8 key-frags][4] ----
            float sc[2][8][4];
#pragma unroll
            for (int mi = 0; mi < 2; mi++)
#pragma unroll
                for (int j = 0; j < 8; j++)
#pragma unroll
                    for (int c = 0; c < 4; c++) sc[mi][j][c] = 0.f;

#pragma unroll
            for (int ks = 0; ks < 4; ks++) {
                uint32_t af[2][4];
#pragma unroll
                for (int mi = 0; mi < 2; mi++) {
                    int row = wid * 32 + mi * 16 + (lane & 15);
                    int ch = ks * 2 + (lane >> 4);
                    uint32_t off = row * 128 + ((ch ^ (row & 7)) * 16);
                    LDSM_X4(af[mi], sq + off);
                }
#pragma unroll
                for (int jp = 0; jp < 4; jp++) {
                    int j = jp * 2;
                    int row = (j + (lane >> 4)) * 8 + (lane & 7);
                    int ch = ks * 2 + ((lane >> 3) & 1);
                    uint32_t off = row * 128 + ((ch ^ (row & 7)) * 16);
                    uint32_t bf[4];
                    LDSM_X4(bf, sk + off);
#pragma unroll
                    for (int mi = 0; mi < 2; mi++) {
                        MMA16816H(sc[mi][j],     af[mi], (&bf[0]));
                        MMA16816H(sc[mi][j + 1], af[mi], (&bf[2]));
                    }
                }
            }

            // ---- scale (base-2) + causal mask ----
            bool diag = (kt * 64 + 63 > wrow);
#pragma unroll
            for (int mi = 0; mi < 2; mi++) {
                int qr = wrow + mi * 16 + (lane >> 2);
#pragma unroll
                for (int j = 0; j < 8; j++) {
                    int col = kt * 64 + j * 8 + (lane & 3) * 2;
#pragma unroll
                    for (int c = 0; c < 4; c++) {
                        float v = sc[mi][j][c] * kscale;
                        if (diag) {
                            int cc = col + (c & 1);
                            int rr = qr + ((c >= 2) ? 8 : 0);
                            if (cc > rr) v = -1e30f;
                        }
                        sc[mi][j][c] = v;
                    }
                }
            }

            // ---- online softmax (base-2), per mi ----
            uint32_t ph[2][4][4];
#pragma unroll
            for (int mi = 0; mi < 2; mi++) {
                float mt0 = -1e30f, mt1 = -1e30f;
#pragma unroll
                for (int j = 0; j < 8; j++) {
                    mt0 = fmaxf(mt0, fmaxf(sc[mi][j][0], sc[mi][j][1]));
                    mt1 = fmaxf(mt1, fmaxf(sc[mi][j][2], sc[mi][j][3]));
                }
                mt0 = fmaxf(mt0, __shfl_xor_sync(0xffffffffu, mt0, 1));
                mt0 = fmaxf(mt0, __shfl_xor_sync(0xffffffffu, mt0, 2));
                mt1 = fmaxf(mt1, __shfl_xor_sync(0xffffffffu, mt1, 1));
                mt1 = fmaxf(mt1, __shfl_xor_sync(0xffffffffu, mt1, 2));

                float mn0 = fmaxf(m[mi][0], mt0), mn1 = fmaxf(m[mi][1], mt1);
                float corr0 = exp2f(m[mi][0] - mn0), corr1 = exp2f(m[mi][1] - mn1);

                float ps0 = 0.f, ps1 = 0.f;
#pragma unroll
                for (int ks = 0; ks < 4; ks++) {
                    uint32_t t0 = packh2(sc[mi][2*ks][0]   - mn0, sc[mi][2*ks][1]   - mn0);
                    uint32_t t1 = packh2(sc[mi][2*ks][2]   - mn1, sc[mi][2*ks][3]   - mn1);
                    uint32_t t2 = packh2(sc[mi][2*ks+1][0] - mn0, sc[mi][2*ks+1][1] - mn0);
                    uint32_t t3 = packh2(sc[mi][2*ks+1][2] - mn1, sc[mi][2*ks+1][3] - mn1);
                    EX2_F16X2(ph[mi][ks][0], t0);
                    EX2_F16X2(ph[mi][ks][1], t1);
                    EX2_F16X2(ph[mi][ks][2], t2);
                    EX2_F16X2(ph[mi][ks][3], t3);
                    float2 f0 = __half22float2(*(__half2*)&ph[mi][ks][0]);
                    float2 f1 = __half22float2(*(__half2*)&ph[mi][ks][1]);
                    float2 f2 = __half22float2(*(__half2*)&ph[mi][ks][2]);
                    float2 f3 = __half22float2(*(__half2*)&ph[mi][ks][3]);
                    ps0 += f0.x + f0.y + f2.x + f2.y;
                    ps1 += f1.x + f1.y + f3.x + f3.y;
                }
                ps0 += __shfl_xor_sync(0xffffffffu, ps0, 1);
                ps0 += __shfl_xor_sync(0xffffffffu, ps0, 2);
                ps1 += __shfl_xor_sync(0xffffffffu, ps1, 1);
                ps1 += __shfl_xor_sync(0xffffffffu, ps1, 2);

                l[mi][0] = l[mi][0] * corr0 + ps0; m[mi][0] = mn0;
                l[mi][1] = l[mi][1] * corr1 + ps1; m[mi][1] = mn1;
#pragma unroll
                for (int j = 0; j < 8; j++) {
                    o[mi][j][0] *= corr0; o[mi][j][1] *= corr0;
                    o[mi][j][2] *= corr1; o[mi][j][3] *= corr1;
                }
            }

            // ---- O += P V (V frags shared across mi) ----
#pragma unroll
            for (int ks = 0; ks < 4; ks++) {
#pragma unroll
                for (int j = 0; j < 4; j++) {
                    uint32_t bf[4];
                    int row = ks * 16 + (lane & 15);
                    int ch = j * 2 + (lane >> 4);
                    uint32_t off = row * 128 + ((ch ^ (row & 7)) * 16);
                    LDSM_X4T(bf, sv + off);
#pragma unroll
                    for (int mi = 0; mi < 2; mi++) {
                        MMA16816H(o[mi][2*j],     ph[mi][ks], (&bf[0]));
                        MMA16816H(o[mi][2*j + 1], ph[mi][ks], (&bf[2]));
                    }
                }
            }
        }
        __syncthreads();
    }

    // ---- normalize + single-fp16 store (for Wo GEMM) ----
#pragma unroll
    for (int mi = 0; mi < 2; mi++) {
        float inv0 = 1.f / l[mi][0], inv1 = 1.f / l[mi][1];
        const int row0 = b * SEQ + qt * 128 + wid * 32 + mi * 16 + (lane >> 2);
#pragma unroll
        for (int j = 0; j < 8; j++) {
            float a0 = o[mi][j][0] * inv0, a1 = o[mi][j][1] * inv0;
            float a2 = o[mi][j][2] * inv1, a3 = o[mi][j][3] * inv1;
            size_t off0 = (size_t)row0 * EMB + h * HDIM + j * 8 + (lane & 3) * 2;
            size_t off1 = off0 + (size_t)8 * EMB;
            *(uint32_t*)&Oh[off0] = packh2(a0, a1);
            *(uint32_t*)&Oh[off1] = packh2(a2, a3);
        }
    }
}

// ======================= Scratch =======================
__device__ __half g_xh[TOK * EMB];
__device__ __half g_qh[TOK * EMB], g_kh[TOK * EMB], g_vh[TOK * EMB];
__device__ __half g_ah[TOK * EMB];
__device__ __half g_wq[EMB * EMB], g_wk[EMB * EMB], g_wv[EMB * EMB], g_wo[EMB * EMB];

extern "C" void kernel_launch(void* const* d_in, const int* in_sizes, int n_in,
                              void* d_out, int out_size) {
    const float* x  = (const float*)d_in[0];
    const float* Wq = (const float*)d_in[2];
    const float* Wk = (const float*)d_in[3];
    const float* Wv = (const float*)d_in[4];
    const float* Wo = (const float*)d_in[5];
    float* out = (float*)d_out;

    __half *xh, *qh, *kh, *vh, *ah, *wq, *wk, *wv, *wo;
    cudaGetSymbolAddress((void**)&xh, g_xh);
    cudaGetSymbolAddress((void**)&qh, g_qh);
    cudaGetSymbolAddress((void**)&kh, g_kh);
    cudaGetSymbolAddress((void**)&vh, g_vh);
    cudaGetSymbolAddress((void**)&ah, g_ah);
    cudaGetSymbolAddress((void**)&wq, g_wq);
    cudaGetSymbolAddress((void**)&wk, g_wk);
    cudaGetSymbolAddress((void**)&wv, g_wv);
    cudaGetSymbolAddress((void**)&wo, g_wo);

    static bool attrs_set = false;
    if (!attrs_set) {
        cudaFuncSetAttribute(gemm_qkv_kernel,
                             cudaFuncAttributeMaxDynamicSharedMemorySize, GEMM_SMEM);
        cudaFuncSetAttribute(gemm_o_kernel,
                             cudaFuncAttributeMaxDynamicSharedMemorySize, GEMM_SMEM);
        cudaFuncSetAttribute(attn_mma_kernel,
                             cudaFuncAttributeMaxDynamicSharedMemorySize, ATTN_SMEM);
        attrs_set = true;
    }

    const int XB = (TOK * EMB / 4 + 255) / 256;
    dim3 cvtGrid(XB, 5);
    cvt_all_kernel<<<cvtGrid, 256>>>(x, Wq, Wk, Wv, Wo, xh, wq, wk, wv, wo);

    dim3 qkvGrid(EMB / NT, TOK / MT, 3);   // (8, 32, 3)
    gemm_qkv_kernel<<<qkvGrid, 128, GEMM_SMEM>>>(xh, wq, wk, wv, qh, kh, vh);

    dim3 attnGrid(SEQ / 128, HEADS, BATCH);   // (16, 16, 2)
    attn_mma_kernel<<<attnGrid, 128, ATTN_SMEM>>>(qh, kh, vh, ah);

    dim3 oGrid(EMB / NT, TOK / MT);   // (8, 32)
    gemm_o_kernel<<<oGrid, 128, GEMM_SMEM>>>(ah, wo, out);
}